// round 7
// baseline (speedup 1.0000x reference)
#include <cuda_runtime.h>
#include <cstdint>

// Identity (ifft(fft(x)).real == x, rel_err ~1.3e-7 << 1e-3 tolerance).
// Measured at ~7.50 TB/s aggregate (94% of HBM spec), the path-independent
// LTS ceiling. Final lever: persistent grid-stride at exactly one wave
// (148 SMs x 8 blocks = 1184 blocks, warp-limited occupancy), eliminating
// ~13 wave transitions of DRAM-queue drain. Inner pattern is the winning
// x2 MLP shape with streaming hints.

__global__ __launch_bounds__(256) void identity_copy_persist(
    const float4* __restrict__ in, float4* __restrict__ out, int n4)
{
    const int step = gridDim.x * blockDim.x * 2;       // 1,212,416 float4
    int base = blockIdx.x * (blockDim.x * 2) + threadIdx.x;
    const int s = blockDim.x;

    // Fast path: both lanes of the x2 pair in range.
    for (; base + s < n4; base += step) {
        float4 a = __ldcs(in + base);
        float4 b = __ldcs(in + base + s);
        __stcs(out + base,     a);
        __stcs(out + base + s, b);
    }
    // Remainder (at most one partial pair per thread).
    if (base < n4) {
        __stcs(out + base, __ldcs(in + base));
    }
}

__global__ __launch_bounds__(256) void identity_copy_tail(
    const float* __restrict__ in, float* __restrict__ out, int start, int n)
{
    int i = start + blockIdx.x * blockDim.x + threadIdx.x;
    if (i < n) out[i] = in[i];
}

extern "C" void kernel_launch(void* const* d_in, const int* in_sizes, int n_in,
                              void* d_out, int out_size)
{
    const float* x = (const float*)d_in[0];
    float* out = (float*)d_out;
    int n = in_sizes[0];           // 33,554,432

    int n4 = n / 4;                // 8,388,608 float4
    if (n4 > 0) {
        const int threads = 256;
        const int blocks = 148 * 8;  // one full wave at warp-limited occupancy
        identity_copy_persist<<<blocks, threads>>>(
            (const float4*)x, (float4*)out, n4);
    }
    int tail_start = n4 * 4;
    if (n - tail_start > 0) {
        identity_copy_tail<<<1, 256>>>(x, out, tail_start, n);
    }
}

// round 8
// speedup vs baseline: 1.0941x; 1.0941x over previous
#include <cuda_runtime.h>
#include <cstdint>

// FINAL — FourierFFTLayer == identity (ifft(fft(x)).real, rel_err ~1.3e-7).
// Pure HBM-bound copy: 256 MB aggregate traffic at ~7.50 TB/s (94% of spec),
// the path-independent LTS ceiling. Design space measured: unroll x1/x2/x4/x8
// flat grids, copy-engine memcpy, persistent one-wave grid — x2 flat wins
// (35.8us kernel). MLP=2 per thread, 16384 blocks for scheduler-side load
// balancing across SM speed variance, streaming (.cs) hints on both streams
// (zero reuse), guard-free fast path on the exact-divide shape.

__global__ __launch_bounds__(256) void identity_copy_f4x2(
    const float4* __restrict__ in, float4* __restrict__ out, int n4)
{
    int base = blockIdx.x * (blockDim.x * 2) + threadIdx.x;
    const int s = blockDim.x;

    if (base + s < n4) {
        float4 a = __ldcs(in + base);
        float4 b = __ldcs(in + base + s);
        __stcs(out + base,     a);
        __stcs(out + base + s, b);
    } else {
        #pragma unroll
        for (int k = 0; k < 2; k++) {
            int i = base + k * s;
            if (i < n4) __stcs(out + i, __ldcs(in + i));
        }
    }
}

__global__ __launch_bounds__(256) void identity_copy_tail(
    const float* __restrict__ in, float* __restrict__ out, int start, int n)
{
    int i = start + blockIdx.x * blockDim.x + threadIdx.x;
    if (i < n) out[i] = in[i];
}

extern "C" void kernel_launch(void* const* d_in, const int* in_sizes, int n_in,
                              void* d_out, int out_size)
{
    const float* x = (const float*)d_in[0];
    float* out = (float*)d_out;
    int n = in_sizes[0];           // 33,554,432

    int n4 = n / 4;                // 8,388,608 float4
    if (n4 > 0) {
        const int threads = 256;
        const int per_block = threads * 2;             // 512 float4 / block
        int blocks = (n4 + per_block - 1) / per_block; // 16384
        identity_copy_f4x2<<<blocks, threads>>>(
            (const float4*)x, (float4*)out, n4);
    }
    int tail_start = n4 * 4;
    if (n - tail_start > 0) {
        identity_copy_tail<<<1, 256>>>(x, out, tail_start, n);
    }
}